// round 1
// baseline (speedup 1.0000x reference)
#include <cuda_runtime.h>
#include <cstdint>

#define D 128
#define MAXN 100000
#define NEG_SLOPE 0.01f

// ---------------- scratch (static device globals; no allocation) ----------------
static __device__ float g_vl[3][D];                 // W1^T @ w2_left per relation
static __device__ float g_vr[3][D];                 // W1^T @ w2_right per relation
static __device__ float g_M[D * D];                 // Wq^T @ Wk
static __device__ float g_sl[3][MAXN];              // per-node left score
static __device__ float g_sr[3][MAXN];              // per-node right score
static __device__ float g_den[3][MAXN];             // softmax denominators
static __device__ float g_hun[3][(size_t)MAXN * D]; // unnormalized aggregation (153.6MB)

// ---------------- K0a: v_l / v_r vectors (6 blocks x 128 threads) ----------------
__global__ void k_vec(const float* __restrict__ W1_0, const float* __restrict__ W1_1,
                      const float* __restrict__ W1_2, const float* __restrict__ w2_0,
                      const float* __restrict__ w2_1, const float* __restrict__ w2_2) {
    int r = blockIdx.x >> 1;
    int half = blockIdx.x & 1;
    const float* W1 = (r == 0) ? W1_0 : (r == 1) ? W1_1 : W1_2;
    const float* w2 = ((r == 0) ? w2_0 : (r == 1) ? w2_1 : w2_2) + half * D;
    int j = threadIdx.x;
    float s = 0.f;
#pragma unroll 8
    for (int i = 0; i < D; i++) s += W1[i * D + j] * w2[i];
    if (half) g_vr[r][j] = s; else g_vl[r][j] = s;
}

// ---------------- K0b: M = Wq^T @ Wk (128 blocks x 128 threads) ----------------
__global__ void k_M(const float* __restrict__ Wq, const float* __restrict__ Wk) {
    int dd = blockIdx.x;
    int j = threadIdx.x;
    float s = 0.f;
#pragma unroll 8
    for (int e = 0; e < D; e++) s += Wq[e * D + dd] * Wk[e * D + j];
    g_M[dd * D + j] = s;
}

// ---------------- K1a: zero scratch ----------------
__global__ void k_zero(int n) {
    size_t total4 = (size_t)3 * n * D / 4;     // float4 count for g_hun
    float4* hp = (float4*)&g_hun[0][0];
    float4 z = make_float4(0.f, 0.f, 0.f, 0.f);
    size_t stride = (size_t)gridDim.x * blockDim.x;
    for (size_t i = (size_t)blockIdx.x * blockDim.x + threadIdx.x; i < total4; i += stride)
        hp[i] = z;
    float* dp = &g_den[0][0];
    size_t dtot = (size_t)3 * MAXN;
    for (size_t i = (size_t)blockIdx.x * blockDim.x + threadIdx.x; i < dtot; i += stride)
        dp[i] = 0.f;
}

// ---------------- K1b: per-node scores, warp per node ----------------
__global__ void k_scores(const float* __restrict__ Nmat, int n) {
    int w = (blockIdx.x * blockDim.x + threadIdx.x) >> 5;
    int lane = threadIdx.x & 31;
    if (w >= n) return;
    float4 x = ((const float4*)(Nmat + (size_t)w * D))[lane];
    float p0, p1, p2, p3, p4, p5;
    {
        float4 a = ((const float4*)g_vl[0])[lane];
        float4 b = ((const float4*)g_vr[0])[lane];
        p0 = x.x * a.x + x.y * a.y + x.z * a.z + x.w * a.w;
        p1 = x.x * b.x + x.y * b.y + x.z * b.z + x.w * b.w;
    }
    {
        float4 a = ((const float4*)g_vl[1])[lane];
        float4 b = ((const float4*)g_vr[1])[lane];
        p2 = x.x * a.x + x.y * a.y + x.z * a.z + x.w * a.w;
        p3 = x.x * b.x + x.y * b.y + x.z * b.z + x.w * b.w;
    }
    {
        float4 a = ((const float4*)g_vl[2])[lane];
        float4 b = ((const float4*)g_vr[2])[lane];
        p4 = x.x * a.x + x.y * a.y + x.z * a.z + x.w * a.w;
        p5 = x.x * b.x + x.y * b.y + x.z * b.z + x.w * b.w;
    }
#pragma unroll
    for (int o = 16; o; o >>= 1) {
        p0 += __shfl_xor_sync(0xFFFFFFFFu, p0, o);
        p1 += __shfl_xor_sync(0xFFFFFFFFu, p1, o);
        p2 += __shfl_xor_sync(0xFFFFFFFFu, p2, o);
        p3 += __shfl_xor_sync(0xFFFFFFFFu, p3, o);
        p4 += __shfl_xor_sync(0xFFFFFFFFu, p4, o);
        p5 += __shfl_xor_sync(0xFFFFFFFFu, p5, o);
    }
    if (lane == 0) {
        g_sl[0][w] = p0; g_sr[0][w] = p1;
        g_sl[1][w] = p2; g_sr[1][w] = p3;
        g_sl[2][w] = p4; g_sr[2][w] = p5;
    }
}

// ---------------- K2: edge pass (warp per edge), one launch per relation ----------------
__global__ void k_edge(const float* __restrict__ Nmat, const int* __restrict__ src,
                       const int* __restrict__ dst, int E, int r) {
    int w = (blockIdx.x * blockDim.x + threadIdx.x) >> 5;
    int lane = threadIdx.x & 31;
    if (w >= E) return;
    int s = src[w];
    int d = dst[w];
    float ev = g_sl[r][s] + g_sr[r][d];
    ev = (ev >= 0.f) ? ev : NEG_SLOPE * ev;
    float ex = __expf(ev);
    if (lane == 0) atomicAdd(&g_den[r][d], ex);
    float4 nv = ((const float4*)(Nmat + (size_t)s * D))[lane];
    float* hp = &g_hun[r][(size_t)d * D + lane * 4];
    asm volatile("red.global.add.v4.f32 [%0], {%1,%2,%3,%4};" ::
                 "l"(hp), "f"(ex * nv.x), "f"(ex * nv.y), "f"(ex * nv.z), "f"(ex * nv.w)
                 : "memory");
}

// ---------------- K3: normalize + cross-relation attention, warp per node ----------------
__global__ void k_final(float* __restrict__ out, int n, const int* __restrict__ tptr) {
    int w = (blockIdx.x * blockDim.x + threadIdx.x) >> 5;
    int lane = threadIdx.x & 31;
    if (w >= n) return;
    int t = tptr ? tptr[0] : 0;
    t = (t < 0) ? 0 : ((t > 2) ? 2 : t);
    size_t base = (size_t)w * D + lane * 4;

    float4 h0, h1, h2;
    {
        float dn = g_den[0][w]; float iv = (dn > 0.f) ? (1.f / dn) : 0.f;
        float4 hu = *(const float4*)&g_hun[0][base];
        h0 = make_float4(hu.x * iv, hu.y * iv, hu.z * iv, hu.w * iv);
    }
    {
        float dn = g_den[1][w]; float iv = (dn > 0.f) ? (1.f / dn) : 0.f;
        float4 hu = *(const float4*)&g_hun[1][base];
        h1 = make_float4(hu.x * iv, hu.y * iv, hu.z * iv, hu.w * iv);
    }
    {
        float dn = g_den[2][w]; float iv = (dn > 0.f) ? (1.f / dn) : 0.f;
        float4 hu = *(const float4*)&g_hun[2][base];
        h2 = make_float4(hu.x * iv, hu.y * iv, hu.z * iv, hu.w * iv);
    }

    float4 ht = (t == 0) ? h0 : ((t == 1) ? h1 : h2);

    // u = ht @ M  (ht distributed across lanes; broadcast via shfl)
    float4 u = make_float4(0.f, 0.f, 0.f, 0.f);
    const float4* M4 = (const float4*)g_M;
#pragma unroll
    for (int s = 0; s < 32; s++) {
        float hx = __shfl_sync(0xFFFFFFFFu, ht.x, s);
        float hy = __shfl_sync(0xFFFFFFFFu, ht.y, s);
        float hz = __shfl_sync(0xFFFFFFFFu, ht.z, s);
        float hw = __shfl_sync(0xFFFFFFFFu, ht.w, s);
        int d0 = s * 4;
        float4 m;
        m = M4[(d0 + 0) * 32 + lane];
        u.x += hx * m.x; u.y += hx * m.y; u.z += hx * m.z; u.w += hx * m.w;
        m = M4[(d0 + 1) * 32 + lane];
        u.x += hy * m.x; u.y += hy * m.y; u.z += hy * m.z; u.w += hy * m.w;
        m = M4[(d0 + 2) * 32 + lane];
        u.x += hz * m.x; u.y += hz * m.y; u.z += hz * m.z; u.w += hz * m.w;
        m = M4[(d0 + 3) * 32 + lane];
        u.x += hw * m.x; u.y += hw * m.y; u.z += hw * m.z; u.w += hw * m.w;
    }

    float e0 = u.x * h0.x + u.y * h0.y + u.z * h0.z + u.w * h0.w;
    float e1 = u.x * h1.x + u.y * h1.y + u.z * h1.z + u.w * h1.w;
    float e2 = u.x * h2.x + u.y * h2.y + u.z * h2.z + u.w * h2.w;
#pragma unroll
    for (int o = 16; o; o >>= 1) {
        e0 += __shfl_xor_sync(0xFFFFFFFFu, e0, o);
        e1 += __shfl_xor_sync(0xFFFFFFFFu, e1, o);
        e2 += __shfl_xor_sync(0xFFFFFFFFu, e2, o);
    }
    const float sc = 0.0883883476483184f;  // 1/sqrt(128)
    e0 *= sc; e1 *= sc; e2 *= sc;
    float mx = fmaxf(e0, fmaxf(e1, e2));
    float a0 = __expf(e0 - mx), a1 = __expf(e1 - mx), a2 = __expf(e2 - mx);
    float is = 1.f / (a0 + a1 + a2);
    a0 *= is; a1 *= is; a2 *= is;

    float4 o4;
    o4.x = a0 * h0.x + a1 * h1.x + a2 * h2.x;
    o4.y = a0 * h0.y + a1 * h1.y + a2 * h2.y;
    o4.z = a0 * h0.z + a1 * h1.z + a2 * h2.z;
    o4.w = a0 * h0.w + a1 * h1.w + a2 * h2.w;
    *(float4*)(out + base) = o4;
}

// ---------------- launcher ----------------
extern "C" void kernel_launch(void* const* d_in, const int* in_sizes, int n_in,
                              void* d_out, int out_size) {
    const float* Nmat = (const float*)d_in[0];
    const float* W1_0 = (const float*)d_in[1];
    const float* W1_1 = (const float*)d_in[2];
    const float* W1_2 = (const float*)d_in[3];
    const float* w2_0 = (const float*)d_in[4];
    const float* w2_1 = (const float*)d_in[5];
    const float* w2_2 = (const float*)d_in[6];
    const float* Wq   = (const float*)d_in[7];
    const float* Wk   = (const float*)d_in[8];
    // d_in[9] = Wv : unused in reference output
    const int* src[3] = {(const int*)d_in[10], (const int*)d_in[12], (const int*)d_in[14]};
    const int* dst[3] = {(const int*)d_in[11], (const int*)d_in[13], (const int*)d_in[15]};
    const int* tptr = (n_in > 16) ? (const int*)d_in[16] : nullptr;

    int n = in_sizes[0] / D;
    if (n > MAXN) n = MAXN;

    k_vec<<<6, 128>>>(W1_0, W1_1, W1_2, w2_0, w2_1, w2_2);
    k_M<<<128, 128>>>(Wq, Wk);
    k_zero<<<4096, 256>>>(n);

    int nb_scores = (n + 7) / 8;  // 8 warps per 256-thread block
    k_scores<<<nb_scores, 256>>>(Nmat, n);

    for (int r = 0; r < 3; r++) {
        int E = in_sizes[10 + 2 * r];
        int nb = (E + 7) / 8;
        k_edge<<<nb, 256>>>(Nmat, src[r], dst[r], E, r);
    }

    int nb_final = (n + 7) / 8;
    k_final<<<nb_final, 256>>>((float*)d_out, n, tptr);
}

// round 2
// speedup vs baseline: 1.1163x; 1.1163x over previous
#include <cuda_runtime.h>
#include <cstdint>

#define D 128
#define MAXN 100000
#define MAXE 600000
#define NEG_SLOPE 0.01f

// ---------------- scratch (static device globals; no allocation) ----------------
static __device__ float g_vl[3][D];            // W1^T @ w2_left per relation
static __device__ float g_vr[3][D];            // W1^T @ w2_right per relation
static __device__ float g_M[D * D];            // Wq^T @ Wk
static __device__ float g_sl[3][MAXN];         // per-node left score
static __device__ float g_sr[3][MAXN];         // per-node right score
static __device__ int   g_cnt[3][MAXN];        // in-degree counts
static __device__ int   g_cur[3][MAXN];        // scatter cursors
static __device__ int   g_off[3][MAXN + 1];    // CSR offsets
static __device__ int   g_esrc[3][MAXE];       // sorted-by-dst edge src
static __device__ float g_eex[3][MAXE];        // sorted-by-dst edge exp-score

// ---------------- K0a: v_l / v_r vectors ----------------
__global__ void k_vec(const float* __restrict__ W1_0, const float* __restrict__ W1_1,
                      const float* __restrict__ W1_2, const float* __restrict__ w2_0,
                      const float* __restrict__ w2_1, const float* __restrict__ w2_2) {
    int r = blockIdx.x >> 1;
    int half = blockIdx.x & 1;
    const float* W1 = (r == 0) ? W1_0 : (r == 1) ? W1_1 : W1_2;
    const float* w2 = ((r == 0) ? w2_0 : (r == 1) ? w2_1 : w2_2) + half * D;
    int j = threadIdx.x;
    float s = 0.f;
#pragma unroll 8
    for (int i = 0; i < D; i++) s += W1[i * D + j] * w2[i];
    if (half) g_vr[r][j] = s; else g_vl[r][j] = s;
}

// ---------------- K0b: M = Wq^T @ Wk ----------------
__global__ void k_M(const float* __restrict__ Wq, const float* __restrict__ Wk) {
    int dd = blockIdx.x;
    int j = threadIdx.x;
    float s = 0.f;
#pragma unroll 8
    for (int e = 0; e < D; e++) s += Wq[e * D + dd] * Wk[e * D + j];
    g_M[dd * D + j] = s;
}

// ---------------- K1: zero counts + cursors ----------------
__global__ void k_zero() {
    int i = blockIdx.x * blockDim.x + threadIdx.x;
    int tot = 3 * MAXN;
    int stride = gridDim.x * blockDim.x;
    for (; i < tot; i += stride) {
        (&g_cnt[0][0])[i] = 0;
        (&g_cur[0][0])[i] = 0;
    }
}

// ---------------- K2: per-node scores, warp per node ----------------
__global__ void k_scores(const float* __restrict__ Nmat, int n) {
    int w = (blockIdx.x * blockDim.x + threadIdx.x) >> 5;
    int lane = threadIdx.x & 31;
    if (w >= n) return;
    float4 x = ((const float4*)(Nmat + (size_t)w * D))[lane];
    float p0, p1, p2, p3, p4, p5;
    {
        float4 a = ((const float4*)g_vl[0])[lane];
        float4 b = ((const float4*)g_vr[0])[lane];
        p0 = x.x * a.x + x.y * a.y + x.z * a.z + x.w * a.w;
        p1 = x.x * b.x + x.y * b.y + x.z * b.z + x.w * b.w;
    }
    {
        float4 a = ((const float4*)g_vl[1])[lane];
        float4 b = ((const float4*)g_vr[1])[lane];
        p2 = x.x * a.x + x.y * a.y + x.z * a.z + x.w * a.w;
        p3 = x.x * b.x + x.y * b.y + x.z * b.z + x.w * b.w;
    }
    {
        float4 a = ((const float4*)g_vl[2])[lane];
        float4 b = ((const float4*)g_vr[2])[lane];
        p4 = x.x * a.x + x.y * a.y + x.z * a.z + x.w * a.w;
        p5 = x.x * b.x + x.y * b.y + x.z * b.z + x.w * b.w;
    }
#pragma unroll
    for (int o = 16; o; o >>= 1) {
        p0 += __shfl_xor_sync(0xFFFFFFFFu, p0, o);
        p1 += __shfl_xor_sync(0xFFFFFFFFu, p1, o);
        p2 += __shfl_xor_sync(0xFFFFFFFFu, p2, o);
        p3 += __shfl_xor_sync(0xFFFFFFFFu, p3, o);
        p4 += __shfl_xor_sync(0xFFFFFFFFu, p4, o);
        p5 += __shfl_xor_sync(0xFFFFFFFFu, p5, o);
    }
    if (lane == 0) {
        g_sl[0][w] = p0; g_sr[0][w] = p1;
        g_sl[1][w] = p2; g_sr[1][w] = p3;
        g_sl[2][w] = p4; g_sr[2][w] = p5;
    }
}

// ---------------- K3: in-degree counts ----------------
__global__ void k_count(const int* __restrict__ dst, int E, int r) {
    int t = blockIdx.x * blockDim.x + threadIdx.x;
    if (t >= E) return;
    atomicAdd(&g_cnt[r][dst[t]], 1);
}

// ---------------- K4: exclusive scan -> CSR offsets (1 block of 1024 per relation) ----------------
__global__ void k_scan(int n) {
    int r = blockIdx.x;
    __shared__ int warpsum[32];
    int tid = threadIdx.x;                     // 0..1023
    int lane = tid & 31, wid = tid >> 5;
    int chunk = (n + 1023) >> 10;
    int beg = tid * chunk;
    int end = beg + chunk; if (end > n) end = n;
    if (beg > n) beg = n;
    int loc = 0;
    for (int i = beg; i < end; i++) loc += g_cnt[r][i];
    // inclusive scan across block
    int v = loc;
#pragma unroll
    for (int o = 1; o < 32; o <<= 1) {
        int t = __shfl_up_sync(0xFFFFFFFFu, v, o);
        if (lane >= o) v += t;
    }
    if (lane == 31) warpsum[wid] = v;
    __syncthreads();
    if (wid == 0) {
        int s = warpsum[lane];
#pragma unroll
        for (int o = 1; o < 32; o <<= 1) {
            int t = __shfl_up_sync(0xFFFFFFFFu, s, o);
            if (lane >= o) s += t;
        }
        warpsum[lane] = s;
    }
    __syncthreads();
    int excl = v - loc + (wid ? warpsum[wid - 1] : 0);
    int run = excl;
    for (int i = beg; i < end; i++) {
        g_off[r][i] = run;
        run += g_cnt[r][i];
    }
    if (end == n) g_off[r][n] = run;   // tail threads all write the same total
}

// ---------------- K5: scatter edges into CSR order, with exp-score ----------------
__global__ void k_scatter(const int* __restrict__ src, const int* __restrict__ dst,
                          int E, int r) {
    int t = blockIdx.x * blockDim.x + threadIdx.x;
    if (t >= E) return;
    int s = src[t];
    int d = dst[t];
    float ev = g_sl[r][s] + g_sr[r][d];
    ev = (ev >= 0.f) ? ev : NEG_SLOPE * ev;
    float ex = __expf(ev);
    int pos = g_off[r][d] + atomicAdd(&g_cur[r][d], 1);
    g_esrc[r][pos] = s;
    g_eex[r][pos] = ex;
}

// ---------------- K6: fused aggregation + cross-relation attention (warp per node) ----------------
__global__ void k_agg(const float* __restrict__ Nmat, float* __restrict__ out,
                      int n, const int* __restrict__ tptr) {
    int w = (blockIdx.x * blockDim.x + threadIdx.x) >> 5;
    int lane = threadIdx.x & 31;
    if (w >= n) return;

    const float4* N4 = (const float4*)Nmat;
    float4 h[3];

#pragma unroll
    for (int r = 0; r < 3; r++) {
        int beg = g_off[r][w];
        int end = g_off[r][w + 1];
        float4 acc = make_float4(0.f, 0.f, 0.f, 0.f);
        float den = 0.f;
        for (int base = beg; base < end; base += 32) {
            int cnt = end - base; if (cnt > 32) cnt = 32;
            int sv = 0; float exv = 0.f;
            if (lane < cnt) {
                sv = g_esrc[r][base + lane];
                exv = g_eex[r][base + lane];
            }
            for (int j = 0; j < cnt; j++) {
                int s = __shfl_sync(0xFFFFFFFFu, sv, j);
                float ex = __shfl_sync(0xFFFFFFFFu, exv, j);
                float4 nv = N4[(size_t)s * 32 + lane];
                acc.x += ex * nv.x; acc.y += ex * nv.y;
                acc.z += ex * nv.z; acc.w += ex * nv.w;
                den += ex;
            }
        }
        float iv = (den > 0.f) ? (1.f / den) : 0.f;
        h[r] = make_float4(acc.x * iv, acc.y * iv, acc.z * iv, acc.w * iv);
    }

    int t = tptr ? tptr[0] : 0;
    t = (t < 0) ? 0 : ((t > 2) ? 2 : t);
    float4 ht = (t == 0) ? h[0] : ((t == 1) ? h[1] : h[2]);

    // u = ht @ M  (ht distributed across lanes; broadcast via shfl)
    float4 u = make_float4(0.f, 0.f, 0.f, 0.f);
    const float4* M4 = (const float4*)g_M;
#pragma unroll
    for (int s = 0; s < 32; s++) {
        float hx = __shfl_sync(0xFFFFFFFFu, ht.x, s);
        float hy = __shfl_sync(0xFFFFFFFFu, ht.y, s);
        float hz = __shfl_sync(0xFFFFFFFFu, ht.z, s);
        float hw = __shfl_sync(0xFFFFFFFFu, ht.w, s);
        int d0 = s * 4;
        float4 m;
        m = M4[(d0 + 0) * 32 + lane];
        u.x += hx * m.x; u.y += hx * m.y; u.z += hx * m.z; u.w += hx * m.w;
        m = M4[(d0 + 1) * 32 + lane];
        u.x += hy * m.x; u.y += hy * m.y; u.z += hy * m.z; u.w += hy * m.w;
        m = M4[(d0 + 2) * 32 + lane];
        u.x += hz * m.x; u.y += hz * m.y; u.z += hz * m.z; u.w += hz * m.w;
        m = M4[(d0 + 3) * 32 + lane];
        u.x += hw * m.x; u.y += hw * m.y; u.z += hw * m.z; u.w += hw * m.w;
    }

    float e0 = u.x * h[0].x + u.y * h[0].y + u.z * h[0].z + u.w * h[0].w;
    float e1 = u.x * h[1].x + u.y * h[1].y + u.z * h[1].z + u.w * h[1].w;
    float e2 = u.x * h[2].x + u.y * h[2].y + u.z * h[2].z + u.w * h[2].w;
#pragma unroll
    for (int o = 16; o; o >>= 1) {
        e0 += __shfl_xor_sync(0xFFFFFFFFu, e0, o);
        e1 += __shfl_xor_sync(0xFFFFFFFFu, e1, o);
        e2 += __shfl_xor_sync(0xFFFFFFFFu, e2, o);
    }
    const float sc = 0.0883883476483184f;  // 1/sqrt(128)
    e0 *= sc; e1 *= sc; e2 *= sc;
    float mx = fmaxf(e0, fmaxf(e1, e2));
    float a0 = __expf(e0 - mx), a1 = __expf(e1 - mx), a2 = __expf(e2 - mx);
    float is = 1.f / (a0 + a1 + a2);
    a0 *= is; a1 *= is; a2 *= is;

    float4 o4;
    o4.x = a0 * h[0].x + a1 * h[1].x + a2 * h[2].x;
    o4.y = a0 * h[0].y + a1 * h[1].y + a2 * h[2].y;
    o4.z = a0 * h[0].z + a1 * h[1].z + a2 * h[2].z;
    o4.w = a0 * h[0].w + a1 * h[1].w + a2 * h[2].w;
    *(float4*)(out + (size_t)w * D + lane * 4) = o4;
}

// ---------------- launcher ----------------
extern "C" void kernel_launch(void* const* d_in, const int* in_sizes, int n_in,
                              void* d_out, int out_size) {
    const float* Nmat = (const float*)d_in[0];
    const float* W1_0 = (const float*)d_in[1];
    const float* W1_1 = (const float*)d_in[2];
    const float* W1_2 = (const float*)d_in[3];
    const float* w2_0 = (const float*)d_in[4];
    const float* w2_1 = (const float*)d_in[5];
    const float* w2_2 = (const float*)d_in[6];
    const float* Wq   = (const float*)d_in[7];
    const float* Wk   = (const float*)d_in[8];
    // d_in[9] = Wv : unused in reference output
    const int* src[3] = {(const int*)d_in[10], (const int*)d_in[12], (const int*)d_in[14]};
    const int* dst[3] = {(const int*)d_in[11], (const int*)d_in[13], (const int*)d_in[15]};
    const int* tptr = (n_in > 16) ? (const int*)d_in[16] : nullptr;

    int n = in_sizes[0] / D;
    if (n > MAXN) n = MAXN;

    k_vec<<<6, 128>>>(W1_0, W1_1, W1_2, w2_0, w2_1, w2_2);
    k_M<<<128, 128>>>(Wq, Wk);
    k_zero<<<256, 256>>>();

    int nb_scores = (n + 7) / 8;
    k_scores<<<nb_scores, 256>>>(Nmat, n);

    for (int r = 0; r < 3; r++) {
        int E = in_sizes[10 + 2 * r];
        if (E > MAXE) E = MAXE;
        k_count<<<(E + 255) / 256, 256>>>(dst[r], E, r);
    }
    k_scan<<<3, 1024>>>(n);
    for (int r = 0; r < 3; r++) {
        int E = in_sizes[10 + 2 * r];
        if (E > MAXE) E = MAXE;
        k_scatter<<<(E + 255) / 256, 256>>>(src[r], dst[r], E, r);
    }

    int nb_agg = (n + 7) / 8;
    k_agg<<<nb_agg, 256>>>(Nmat, (float*)d_out, n, tptr);
}